// round 9
// baseline (speedup 1.0000x reference)
#include <cuda_runtime.h>
#include <cuda_fp16.h>
#include <cstdint>

#define IR 1771
#define BSTRIDE (64 * IR)
#define SCALE_PSI 0.04419417382415922f   // 1/sqrt(512)

// ---------------- device scratch (all zero-initialized .bss) ----------------
__device__ __align__(16) __half g_wT[64 * 64 * 512];   // rn w  [p=4096][k=512]
__device__ __align__(16) __half g_DT[1792 * 512];      // rn D^T [m pad 1792][n=512]
__device__ __align__(16) __half g_psiL[4096 * 1792];   // psi*alpha linear [p][m]
__device__ __align__(16) __half g_psiT[7843840];       // per-l [ov][k=i*dp+u]
__device__ __align__(16) __half g_xT[31002624];        // per-l [bm][k=i*dp+u]

__constant__ int c_off[11] = {0, 1, 10, 35, 84, 165, 286, 455, 680, 969, 1330};
__constant__ int c_dp[11]  = {2, 4, 6, 8, 10, 12, 14, 16, 18, 20, 22};
__constant__ int c_PT[11]  = {0, 8192, 57344, 180224, 409600, 778240, 1318912,
                              2064384, 3047424, 4300800, 5857280};
__constant__ int c_XT[11]  = {0, 32768, 229376, 720896, 1638400, 3112960, 5275648,
                              8257536, 12189696, 17203200, 23429120};
// cumulative d*ceil(d/2) block counts (946 total)
__constant__ int c_tB[12]  = {0, 1, 7, 22, 50, 95, 161, 252, 372, 525, 715, 946};
__constant__ float c_invd[11]   = {1.0f, 1.0f/3.0f, 0.2f, 1.0f/7.0f, 1.0f/9.0f, 1.0f/11.0f,
                                   1.0f/13.0f, 1.0f/15.0f, 1.0f/17.0f, 1.0f/19.0f, 1.0f/21.0f};
__constant__ float c_invhdp[11] = {1.0f, 0.5f, 1.0f/3.0f, 0.25f, 0.2f, 1.0f/6.0f,
                                   1.0f/7.0f, 0.125f, 1.0f/9.0f, 0.1f, 1.0f/11.0f};
__constant__ float c_alpha[11]  = {0.125f, 0.072168784f, 0.055901699f, 0.047245559f,
                                   0.041666667f, 0.037688918f, 0.034668700f, 0.032274861f,
                                   0.030316953f, 0.028676967f, 0.027277236f};

// ---------------------------------------------------------------- helpers
__device__ __forceinline__ uint32_t s2u(const void* p) {
    uint32_t a;
    asm("{ .reg .u64 t; cvta.to.shared.u64 t, %1; cvt.u32.u64 %0, t; }" : "=r"(a) : "l"(p));
    return a;
}
__device__ __forceinline__ void mma16(float* c, const uint32_t* a, const uint32_t* b) {
    asm volatile(
        "mma.sync.aligned.m16n8k16.row.col.f32.f16.f16.f32 "
        "{%0,%1,%2,%3}, {%4,%5,%6,%7}, {%8,%9}, {%0,%1,%2,%3};"
        : "+f"(c[0]), "+f"(c[1]), "+f"(c[2]), "+f"(c[3])
        : "r"(a[0]), "r"(a[1]), "r"(a[2]), "r"(a[3]), "r"(b[0]), "r"(b[1]));
}
__device__ __forceinline__ void ldsm4(uint32_t* r, uint32_t addr) {
    asm volatile("ldmatrix.sync.aligned.m8n8.x4.shared.b16 {%0,%1,%2,%3}, [%4];"
                 : "=r"(r[0]), "=r"(r[1]), "=r"(r[2]), "=r"(r[3]) : "r"(addr));
}
__device__ __forceinline__ void cpa16(uint32_t dst, const void* src) {
    asm volatile("cp.async.cg.shared.global [%0], [%1], 16;" :: "r"(dst), "l"(src));
}
#define CP_COMMIT asm volatile("cp.async.commit_group;" ::: "memory")
#define CP_WAIT2  asm volatile("cp.async.wait_group 2;" ::: "memory")

#define STAGE_B 49152u          // 32KB A (256 rows) + 16KB B (128 rows)
#define SMEM_TOTAL (4u * STAGE_B)

// ===========================================================================
// Dense fp16 GEMM core: C[256,128] += A[256,K] * B[128,K]^T (fp32 accum).
// 8 warps (4m x 2n), warp tile 64x64, K-chunk 64, 4-stage cp.async pipeline,
// double-buffered ldmatrix fragments.
// ===========================================================================
__device__ __forceinline__ void gemm_core(const __half* __restrict__ A,
                                          const __half* __restrict__ B,
                                          int K, uint32_t smem,
                                          float (&acc)[4][8][4]) {
    const int tid = threadIdx.x;
    const int lane = tid & 31, wid = tid >> 5;
    const int wm = wid >> 1, wn = wid & 1;

    const int s = tid & 7, rb = tid >> 3;
    const __half* srcA = A + (size_t)rb * K + (s << 3);
    const __half* srcB = B + (size_t)rb * K + (s << 3);
    const uint32_t swz = ((uint32_t)(s ^ (rb & 7))) << 4;
    uint32_t dstOff[12];
#pragma unroll
    for (int q = 0; q < 12; ++q)
        dstOff[q] = (uint32_t)(rb + (q << 5)) * 128u + swz;

    const int Lm = lane & 7, Lmat = lane >> 3;
    const uint32_t h = (uint32_t)(Lmat >> 1);
    uint32_t rowA[4], rowB[4];
#pragma unroll
    for (int mf = 0; mf < 4; ++mf)
        rowA[mf] = (uint32_t)(wm * 64 + mf * 16 + ((Lmat & 1) << 3) + Lm);
#pragma unroll
    for (int pr = 0; pr < 4; ++pr)
        rowB[pr] = (uint32_t)(wn * 64 + pr * 16 + ((Lmat & 1) << 3) + Lm);

    const int nCk = K >> 6;

#pragma unroll
    for (int pc = 0; pc < 3; ++pc) {
        uint32_t st = smem + (uint32_t)pc * STAGE_B;
#pragma unroll
        for (int q = 0; q < 8; ++q)
            cpa16(st + dstOff[q], srcA + (size_t)(q << 5) * K + pc * 64);
#pragma unroll
        for (int q = 8; q < 12; ++q)
            cpa16(st + dstOff[q], srcB + (size_t)((q - 8) << 5) * K + pc * 64);
        CP_COMMIT;
    }

#define LOAD_FRAGS(KS, AF, BF)                                                    \
    do {                                                                          \
        const uint32_t sg_ = ((uint32_t)(KS) << 1) | h;                           \
        _Pragma("unroll")                                                         \
        for (int mf_ = 0; mf_ < 4; ++mf_)                                         \
            ldsm4(AF[mf_], stA + rowA[mf_] * 128u + ((sg_ ^ (rowA[mf_] & 7u)) << 4)); \
        _Pragma("unroll")                                                         \
        for (int pr_ = 0; pr_ < 4; ++pr_)                                         \
            ldsm4(BF[pr_], stB + rowB[pr_] * 128u + ((sg_ ^ (rowB[pr_] & 7u)) << 4)); \
    } while (0)

    for (int ck = 0; ck < nCk; ++ck) {
        CP_WAIT2;
        __syncthreads();

        const int nk = ck + 3;
        if (nk < nCk) {
            uint32_t st = smem + (uint32_t)(nk & 3) * STAGE_B;
#pragma unroll
            for (int q = 0; q < 8; ++q)
                cpa16(st + dstOff[q], srcA + (size_t)(q << 5) * K + nk * 64);
#pragma unroll
            for (int q = 8; q < 12; ++q)
                cpa16(st + dstOff[q], srcB + (size_t)((q - 8) << 5) * K + nk * 64);
        }
        CP_COMMIT;

        const uint32_t stA = smem + (uint32_t)(ck & 3) * STAGE_B;
        const uint32_t stB = stA + 32768u;

        uint32_t afb[2][4][4], bfb[2][4][4];
        LOAD_FRAGS(0, afb[0], bfb[0]);
#pragma unroll
        for (int ks = 0; ks < 4; ++ks) {
            const int cur = ks & 1;
            if (ks < 3) LOAD_FRAGS(ks + 1, afb[cur ^ 1], bfb[cur ^ 1]);
#pragma unroll
            for (int mf = 0; mf < 4; ++mf)
#pragma unroll
                for (int nf = 0; nf < 8; ++nf) {
                    uint32_t b2[2] = { bfb[cur][nf >> 1][nf & 1],
                                       bfb[cur][nf >> 1][(nf & 1) + 2] };
                    mma16(acc[mf][nf], afb[cur][mf], b2);
                }
        }
    }
#undef LOAD_FRAGS
}

// ===========================================================================
// prep kernels
// ===========================================================================
__global__ __launch_bounds__(256) void wround_g(const float* __restrict__ wg) {
    int j = (blockIdx.x * 256 + threadIdx.x) << 2;
    float4 v = *(const float4*)(wg + j);
    g_wT[j + 0] = __float2half_rn(v.x);
    g_wT[j + 1] = __float2half_rn(v.y);
    g_wT[j + 2] = __float2half_rn(v.z);
    g_wT[j + 3] = __float2half_rn(v.w);
}

__global__ __launch_bounds__(256) void dt_g(const float* __restrict__ Dg) {
    __shared__ float t[32][33];
    const int m0 = blockIdx.x << 5, n0 = blockIdx.y << 5;
    const int tx = threadIdx.x & 31, ty = threadIdx.x >> 5;
#pragma unroll
    for (int r = 0; r < 32; r += 8) {
        int m = m0 + tx, n = n0 + ty + r;
        t[ty + r][tx] = (m < IR) ? Dg[(size_t)n * IR + m] : 0.0f;
    }
    __syncthreads();
#pragma unroll
    for (int r = 0; r < 32; r += 8) {
        int m = m0 + ty + r, n = n0 + tx;
        if (m < IR) g_DT[(size_t)m * 512 + n] = __float2half_rn(t[tx][ty + r]);
    }
}

// xT[l][(b*d+m)][i*dp+u] = rn(x[b][i][off + u*d + m]); one (b,i) pair per warp
__global__ __launch_bounds__(256) void xt_g(const float* __restrict__ xg) {
    __shared__ float tile[8][441];
    const int l = blockIdx.y;
    const int d = 2 * l + 1, off = c_off[l], dp = c_dp[l], K = dp << 6, dd = d * d;
    const int P = (blockIdx.x << 3) + (threadIdx.x >> 5);
    const int lane = threadIdx.x & 31;
    const int b = P >> 6, i = P & 63;
    float* tw = tile[threadIdx.x >> 5];

    const float* src = xg + (size_t)b * BSTRIDE + i * IR + off;
    for (int j = lane; j < dd; j += 32) tw[j] = src[j];
    __syncwarp();

    const float invd = c_invd[l];
    __half* dst = g_xT + c_XT[l] + (size_t)(b * d) * K + i * dp;
    for (int j = lane; j < dd; j += 32) {
        int m = (int)((float)j * invd + 0.01f);
        int u = j - m * d;
        dst[(size_t)m * K + u] = __float2half_rn(tw[u * d + m]);
    }
}

// ===========================================================================
// psi GEMM: psiL[p,m] = alpha_l(m)/sqrt512 * sum_n wT[p,n] * DT[m,n].
// Grid: 16 tm (p/256) x 14 tn (m/128). Coalesced half2 stores.
// ===========================================================================
__global__ __launch_bounds__(256, 1) void psi_g() {
    extern __shared__ float dsm[];
    const uint32_t smem = s2u(dsm);
    const int tm = blockIdx.x & 15, tn = blockIdx.x >> 4;

    float acc[4][8][4] = {};
    gemm_core(g_wT + (size_t)tm * 256 * 512, g_DT + (size_t)tn * 128 * 512, 512, smem, acc);

    const int lane = threadIdx.x & 31, wid = threadIdx.x >> 5;
    const int wm = wid >> 1, wn = wid & 1;
    const int gid = lane >> 2, tig = lane & 3;
    const int pbase = (tm << 8) + wm * 64 + gid;
    const int mbase = (tn << 7) + wn * 64 + (tig << 1);
#pragma unroll
    for (int nf = 0; nf < 8; ++nf) {
        int m = mbase + nf * 8;
        // per-element alpha (pair may straddle an l boundary)
        float a0 = 0.0f, a1 = 0.0f;
        if (m < IR) {
            int l0 = 0;
#pragma unroll
            for (int j = 1; j < 11; ++j) l0 += (m >= c_off[j]);
            a0 = c_alpha[l0] * SCALE_PSI;
            int l1 = (l0 < 10 && (m + 1) >= c_off[l0 + 1]) ? l0 + 1 : l0;
            a1 = ((m + 1) < IR) ? c_alpha[l1] * SCALE_PSI : 0.0f;
        }
#pragma unroll
        for (int mf = 0; mf < 4; ++mf)
#pragma unroll
            for (int i2 = 0; i2 < 2; ++i2) {
                int p = pbase + mf * 16 + (i2 << 3);
                __half2 v2 = __floats2half2_rn(acc[mf][nf][i2 * 2] * a0,
                                               acc[mf][nf][i2 * 2 + 1] * a1);
                *(__half2*)(g_psiL + (size_t)p * 1792 + m) = v2;
            }
    }
}

// ===========================================================================
// pT_g: psiT[l][(o*d+v)][i*dp+u] = psiL[i*64+o][off + u*d + v]  (pad u=d -> 0)
// One warp per (i,o); all stores 4B-aligned half2.
// ===========================================================================
__global__ __launch_bounds__(256) void pT_g() {
    __shared__ __half sm[8][448];
    const int l = blockIdx.y;
    const int d = 2 * l + 1, off = c_off[l], dp = c_dp[l], dd = d * d;
    const int K = dp << 6;
    const int w = threadIdx.x >> 5, lane = threadIdx.x & 31;
    const int P = (blockIdx.x << 3) + w;
    const int i = P >> 6, o = P & 63;
    __half* tw = sm[w];

    const __half* src = g_psiL + (size_t)(i * 64 + o) * 1792 + off;
    for (int j = lane; j < dd; j += 32) tw[j] = src[j];
    __syncwarp();

    const int hdp = dp >> 1;
    const float invh = c_invhdp[l];
    const int tasks = d * hdp;
    const __half hz = __ushort_as_half((unsigned short)0);
    __half* dstBase = g_psiT + c_PT[l] + (size_t)(o * d) * K + i * dp;
    for (int t = lane; t < tasks; t += 32) {
        int v = (int)((float)t * invh + 0.001f);
        int c = t - v * hdp;
        int u0 = c << 1;
        __half h0 = (u0 < d) ? tw[u0 * d + v] : hz;
        __half h1 = (u0 + 1 < d) ? tw[(u0 + 1) * d + v] : hz;
        *(__half2*)(dstBase + (size_t)v * K + u0) = __halves2half2(h0, h1);
    }
}

// ===========================================================================
// so3 GEMM: per l, C[bm,ov] = sum_k xT[bm,k] * psiT[ov,k], K=64*dp (alpha
// pre-folded into psiT). Epilogue staged via smem, m-contiguous runs.
// ===========================================================================
__global__ __launch_bounds__(256, 1) void so3_g(float* __restrict__ outg) {
    extern __shared__ float dsm[];
    const uint32_t smem = s2u(dsm);
    const int idx = 945 - blockIdx.x;        // big-l tiles first
    int l = 0;
#pragma unroll
    for (int j = 1; j < 11; ++j) l += (idx >= c_tB[j]);
    const int d = 2 * l + 1;
    const int dp = c_dp[l];
    const int K = dp << 6;
    const int t0 = idx - c_tB[l];
    const int tile_n = (int)((float)t0 * c_invd[l] + 0.01f);  // t0 / d
    const int tile_m = t0 - tile_n * d;

    float acc[4][8][4] = {};
    gemm_core(g_xT + c_XT[l] + (size_t)tile_m * 256 * K,
              g_psiT + c_PT[l] + (size_t)tile_n * 128 * K, K, smem, acc);

    // ---- stage C tile to smem (132KB, pipeline stages now dead) ----
    __syncthreads();
    float* smC = dsm;
    const int lane = threadIdx.x & 31, wid = threadIdx.x >> 5;
    const int wm = wid >> 1, wn = wid & 1;
    const int gid = lane >> 2, tig = lane & 3;
#pragma unroll
    for (int mf = 0; mf < 4; ++mf)
#pragma unroll
        for (int nf = 0; nf < 8; ++nf)
#pragma unroll
            for (int e = 0; e < 4; ++e) {
                int bml = wm * 64 + mf * 16 + gid + ((e >> 1) << 3);
                int ovl = wn * 64 + nf * 8 + (tig << 1) + (e & 1);
                smC[bml * 129 + ovl] = acc[mf][nf][e];
            }
    __syncthreads();

    // ---- write out in m-contiguous runs ----
    const float invd = c_invd[l];
    const int off = c_off[l];
    const int nValid = d << 6;
    const int B0 = tile_m << 8;
    const int b_first = B0 / d;
    const int m_first = B0 - b_first * d;
    const int nb = (B0 + 255) / d - b_first + 1;
    const int tasks = nb << 7;
    const int tid = threadIdx.x;

    for (int t = tid; t < tasks; t += 256) {
        int j = t >> 7, ovl = t & 127;
        int ov = (tile_n << 7) + ovl;
        if (ov >= nValid) continue;
        int o = (int)((float)ov * invd + 0.01f);
        int v = ov - o * d;
        int start = j * d - m_first;
        int mlo = (start < 0) ? -start : 0;
        int mhi = d;
        { int lim = 256 - start; if (lim < mhi) mhi = lim; }
        if (mlo >= mhi) continue;
        float* gp = outg + (size_t)(b_first + j) * BSTRIDE + o * IR + off + v * d;
        const int sbase = start * 129 + ovl;
        int m = mlo;
        while (m < mhi && (((uintptr_t)(gp + m)) & 15u)) { gp[m] = smC[sbase + m * 129]; ++m; }
        for (; m + 4 <= mhi; m += 4) {
            float4 f;
            f.x = smC[sbase + m * 129];
            f.y = smC[sbase + (m + 1) * 129];
            f.z = smC[sbase + (m + 2) * 129];
            f.w = smC[sbase + (m + 3) * 129];
            *(float4*)(gp + m) = f;
        }
        for (; m < mhi; ++m) gp[m] = smC[sbase + m * 129];
    }
}

// ---------------------------------------------------------------------------
extern "C" void kernel_launch(void* const* d_in, const int* in_sizes, int n_in,
                              void* d_out, int out_size) {
    const float *x = nullptr, *D = nullptr, *w = nullptr;
    for (int i = 0; i < n_in; ++i) {
        int s = in_sizes[i];
        if (s == 256 * 64 * IR) x = (const float*)d_in[i];
        else if (s == 512 * IR) D = (const float*)d_in[i];
        else if (s == 64 * 64 * 512) w = (const float*)d_in[i];
    }

    cudaFuncSetAttribute(psi_g, cudaFuncAttributeMaxDynamicSharedMemorySize, SMEM_TOTAL);
    cudaFuncSetAttribute(so3_g, cudaFuncAttributeMaxDynamicSharedMemorySize, SMEM_TOTAL);

    wround_g<<<2048, 256>>>(w);
    dt_g<<<dim3(56, 16), 256>>>(D);
    xt_g<<<dim3(2048, 11), 256>>>(x);
    psi_g<<<224, 256, SMEM_TOTAL>>>();
    pT_g<<<dim3(512, 11), 256>>>();
    so3_g<<<946, 256, SMEM_TOTAL>>>((float*)d_out);
}

// round 10
// speedup vs baseline: 1.4579x; 1.4579x over previous
#include <cuda_runtime.h>
#include <cuda_fp16.h>
#include <cstdint>

#define IR 1771
#define BSTRIDE (64 * IR)
#define SCALE_PSI 0.04419417382415922f   // 1/sqrt(512)

// ---------------- device scratch (all zero-initialized .bss) ----------------
__device__ __align__(16) __half g_wT[64 * 64 * 512];   // rn w  [p=4096][k=512]
__device__ __align__(16) __half g_DT[1792 * 512];      // rn D^T [m pad 1792][n=512]
__device__ __align__(16) __half g_psiL[4096 * 1792];   // psi*alpha linear [p][m]
__device__ __align__(16) __half g_psiT[7843840];       // per-l [ov][k=i*dp+u]
__device__ __align__(16) __half g_xT[31002624];        // per-l [bm][k=i*dp+u]

__constant__ int c_off[11] = {0, 1, 10, 35, 84, 165, 286, 455, 680, 969, 1330};
__constant__ int c_dp[11]  = {2, 4, 6, 8, 10, 12, 14, 16, 18, 20, 22};
__constant__ int c_PT[11]  = {0, 8192, 57344, 180224, 409600, 778240, 1318912,
                              2064384, 3047424, 4300800, 5857280};
__constant__ int c_XT[11]  = {0, 32768, 229376, 720896, 1638400, 3112960, 5275648,
                              8257536, 12189696, 17203200, 23429120};
// cumulative d*ceil(d/2) block counts (946 total)
__constant__ int c_tB[12]  = {0, 1, 7, 22, 50, 95, 161, 252, 372, 525, 715, 946};
__constant__ float c_invd[11]   = {1.0f, 1.0f/3.0f, 0.2f, 1.0f/7.0f, 1.0f/9.0f, 1.0f/11.0f,
                                   1.0f/13.0f, 1.0f/15.0f, 1.0f/17.0f, 1.0f/19.0f, 1.0f/21.0f};
__constant__ float c_invhdp[11] = {1.0f, 0.5f, 1.0f/3.0f, 0.25f, 0.2f, 1.0f/6.0f,
                                   1.0f/7.0f, 0.125f, 1.0f/9.0f, 0.1f, 1.0f/11.0f};
__constant__ float c_alpha[11]  = {0.125f, 0.072168784f, 0.055901699f, 0.047245559f,
                                   0.041666667f, 0.037688918f, 0.034668700f, 0.032274861f,
                                   0.030316953f, 0.028676967f, 0.027277236f};

// ---------------------------------------------------------------- helpers
__device__ __forceinline__ uint32_t s2u(const void* p) {
    uint32_t a;
    asm("{ .reg .u64 t; cvta.to.shared.u64 t, %1; cvt.u32.u64 %0, t; }" : "=r"(a) : "l"(p));
    return a;
}
__device__ __forceinline__ void mma16(float* c, const uint32_t* a, const uint32_t* b) {
    asm volatile(
        "mma.sync.aligned.m16n8k16.row.col.f32.f16.f16.f32 "
        "{%0,%1,%2,%3}, {%4,%5,%6,%7}, {%8,%9}, {%0,%1,%2,%3};"
        : "+f"(c[0]), "+f"(c[1]), "+f"(c[2]), "+f"(c[3])
        : "r"(a[0]), "r"(a[1]), "r"(a[2]), "r"(a[3]), "r"(b[0]), "r"(b[1]));
}
__device__ __forceinline__ void ldsm4(uint32_t* r, uint32_t addr) {
    asm volatile("ldmatrix.sync.aligned.m8n8.x4.shared.b16 {%0,%1,%2,%3}, [%4];"
                 : "=r"(r[0]), "=r"(r[1]), "=r"(r[2]), "=r"(r[3]) : "r"(addr));
}
__device__ __forceinline__ void cpa16(uint32_t dst, const void* src) {
    asm volatile("cp.async.cg.shared.global [%0], [%1], 16;" :: "r"(dst), "l"(src));
}
#define CP_COMMIT asm volatile("cp.async.commit_group;" ::: "memory")
#define CP_WAIT2  asm volatile("cp.async.wait_group 2;" ::: "memory")

#define STAGE_B 49152u          // 32KB A (256 rows) + 16KB B (128 rows)
#define SMEM_TOTAL (4u * STAGE_B)

// ===========================================================================
// Dense fp16 GEMM core: C[256,128] += A[256,K] * B[128,K]^T (fp32 accum).
// 8 warps (4m x 2n), warp tile 64x64, K-chunk 64, 4-stage cp.async pipeline.
// (round-8 proven single-buffer fragment loop)
// ===========================================================================
__device__ __forceinline__ void gemm_core(const __half* __restrict__ A,
                                          const __half* __restrict__ B,
                                          int K, uint32_t smem,
                                          float (&acc)[4][8][4]) {
    const int tid = threadIdx.x;
    const int lane = tid & 31, wid = tid >> 5;
    const int wm = wid >> 1, wn = wid & 1;

    const int s = tid & 7, rb = tid >> 3;
    const __half* srcA = A + (size_t)rb * K + (s << 3);
    const __half* srcB = B + (size_t)rb * K + (s << 3);
    const uint32_t swz = ((uint32_t)(s ^ (rb & 7))) << 4;
    uint32_t dstOff[12];
#pragma unroll
    for (int q = 0; q < 12; ++q)
        dstOff[q] = (uint32_t)(rb + (q << 5)) * 128u + swz;

    const int Lm = lane & 7, Lmat = lane >> 3;
    const uint32_t h = (uint32_t)(Lmat >> 1);
    uint32_t rowA[4], rowB[4];
#pragma unroll
    for (int mf = 0; mf < 4; ++mf)
        rowA[mf] = (uint32_t)(wm * 64 + mf * 16 + ((Lmat & 1) << 3) + Lm);
#pragma unroll
    for (int pr = 0; pr < 4; ++pr)
        rowB[pr] = (uint32_t)(wn * 64 + pr * 16 + ((Lmat & 1) << 3) + Lm);

    const int nCk = K >> 6;

#pragma unroll
    for (int pc = 0; pc < 3; ++pc) {
        uint32_t st = smem + (uint32_t)pc * STAGE_B;
#pragma unroll
        for (int q = 0; q < 8; ++q)
            cpa16(st + dstOff[q], srcA + (size_t)(q << 5) * K + pc * 64);
#pragma unroll
        for (int q = 8; q < 12; ++q)
            cpa16(st + dstOff[q], srcB + (size_t)((q - 8) << 5) * K + pc * 64);
        CP_COMMIT;
    }

    for (int ck = 0; ck < nCk; ++ck) {
        CP_WAIT2;
        __syncthreads();

        const int nk = ck + 3;
        if (nk < nCk) {
            uint32_t st = smem + (uint32_t)(nk & 3) * STAGE_B;
#pragma unroll
            for (int q = 0; q < 8; ++q)
                cpa16(st + dstOff[q], srcA + (size_t)(q << 5) * K + nk * 64);
#pragma unroll
            for (int q = 8; q < 12; ++q)
                cpa16(st + dstOff[q], srcB + (size_t)((q - 8) << 5) * K + nk * 64);
        }
        CP_COMMIT;

        const uint32_t stA = smem + (uint32_t)(ck & 3) * STAGE_B;
        const uint32_t stB = stA + 32768u;
#pragma unroll
        for (int ks = 0; ks < 4; ++ks) {
            uint32_t af[4][4], bf[4][4];
            const uint32_t sg = (uint32_t)(ks << 1) | h;
#pragma unroll
            for (int mf = 0; mf < 4; ++mf)
                ldsm4(af[mf], stA + rowA[mf] * 128u + ((sg ^ (rowA[mf] & 7u)) << 4));
#pragma unroll
            for (int pr = 0; pr < 4; ++pr)
                ldsm4(bf[pr], stB + rowB[pr] * 128u + ((sg ^ (rowB[pr] & 7u)) << 4));
#pragma unroll
            for (int mf = 0; mf < 4; ++mf)
#pragma unroll
                for (int nf = 0; nf < 8; ++nf) {
                    uint32_t b2[2] = { bf[nf >> 1][nf & 1], bf[nf >> 1][(nf & 1) + 2] };
                    mma16(acc[mf][nf], af[mf], b2);
                }
        }
    }
}

// ===========================================================================
// prep kernels
// ===========================================================================
__global__ __launch_bounds__(256) void wround_g(const float* __restrict__ wg) {
    int j = (blockIdx.x * 256 + threadIdx.x) << 2;
    float4 v = *(const float4*)(wg + j);
    g_wT[j + 0] = __float2half_rn(v.x);
    g_wT[j + 1] = __float2half_rn(v.y);
    g_wT[j + 2] = __float2half_rn(v.z);
    g_wT[j + 3] = __float2half_rn(v.w);
}

__global__ __launch_bounds__(256) void dt_g(const float* __restrict__ Dg) {
    __shared__ float t[32][33];
    const int m0 = blockIdx.x << 5, n0 = blockIdx.y << 5;
    const int tx = threadIdx.x & 31, ty = threadIdx.x >> 5;
#pragma unroll
    for (int r = 0; r < 32; r += 8) {
        int m = m0 + tx, n = n0 + ty + r;
        t[ty + r][tx] = (m < IR) ? Dg[(size_t)n * IR + m] : 0.0f;
    }
    __syncthreads();
#pragma unroll
    for (int r = 0; r < 32; r += 8) {
        int m = m0 + ty + r, n = n0 + tx;
        if (m < IR) g_DT[(size_t)m * 512 + n] = __float2half_rn(t[tx][ty + r]);
    }
}

// xT[l][(b*d+m)][i*dp+u] = rn(x[b][i][off + u*d + m]); one (b,i) pair per warp
__global__ __launch_bounds__(256) void xt_g(const float* __restrict__ xg) {
    __shared__ float tile[8][441];
    const int l = blockIdx.y;
    const int d = 2 * l + 1, off = c_off[l], dp = c_dp[l], K = dp << 6, dd = d * d;
    const int P = (blockIdx.x << 3) + (threadIdx.x >> 5);
    const int lane = threadIdx.x & 31;
    const int b = P >> 6, i = P & 63;
    float* tw = tile[threadIdx.x >> 5];

    const float* src = xg + (size_t)b * BSTRIDE + i * IR + off;
    for (int j = lane; j < dd; j += 32) tw[j] = src[j];
    __syncwarp();

    const float invd = c_invd[l];
    __half* dst = g_xT + c_XT[l] + (size_t)(b * d) * K + i * dp;
    for (int j = lane; j < dd; j += 32) {
        int m = (int)((float)j * invd + 0.01f);
        int u = j - m * d;
        dst[(size_t)m * K + u] = __float2half_rn(tw[u * d + m]);
    }
}

// ===========================================================================
// psi GEMM: psiL[p,m] = alpha_l(m)/sqrt512 * sum_n wT[p,n] * DT[m,n].
// Grid: 16 tm (p/256) x 14 tn (m/128). Coalesced half2 stores.
// ===========================================================================
__global__ __launch_bounds__(256, 1) void psi_g() {
    extern __shared__ float dsm[];
    const uint32_t smem = s2u(dsm);
    const int tm = blockIdx.x & 15, tn = blockIdx.x >> 4;

    float acc[4][8][4] = {};
    gemm_core(g_wT + (size_t)tm * 256 * 512, g_DT + (size_t)tn * 128 * 512, 512, smem, acc);

    const int lane = threadIdx.x & 31, wid = threadIdx.x >> 5;
    const int wm = wid >> 1, wn = wid & 1;
    const int gid = lane >> 2, tig = lane & 3;
    const int pbase = (tm << 8) + wm * 64 + gid;
    const int mbase = (tn << 7) + wn * 64 + (tig << 1);
#pragma unroll
    for (int nf = 0; nf < 8; ++nf) {
        int m = mbase + nf * 8;
        // per-element alpha (pair may straddle an l boundary)
        float a0 = 0.0f, a1 = 0.0f;
        if (m < IR) {
            int l0 = 0;
#pragma unroll
            for (int j = 1; j < 11; ++j) l0 += (m >= c_off[j]);
            a0 = c_alpha[l0] * SCALE_PSI;
            int l1 = (l0 < 10 && (m + 1) >= c_off[l0 + 1]) ? l0 + 1 : l0;
            a1 = ((m + 1) < IR) ? c_alpha[l1] * SCALE_PSI : 0.0f;
        }
#pragma unroll
        for (int mf = 0; mf < 4; ++mf)
#pragma unroll
            for (int i2 = 0; i2 < 2; ++i2) {
                int p = pbase + mf * 16 + (i2 << 3);
                __half2 v2 = __floats2half2_rn(acc[mf][nf][i2 * 2] * a0,
                                               acc[mf][nf][i2 * 2 + 1] * a1);
                *(__half2*)(g_psiL + (size_t)p * 1792 + m) = v2;
            }
    }
}

// ===========================================================================
// pT_g: psiT[l][(o*d+v)][i*dp+u] = psiL[i*64+o][off + u*d + v]  (pad u=d -> 0)
// One warp per (i,o); all stores 4B-aligned half2.
// ===========================================================================
__global__ __launch_bounds__(256) void pT_g() {
    __shared__ __half sm[8][448];
    const int l = blockIdx.y;
    const int d = 2 * l + 1, off = c_off[l], dp = c_dp[l], dd = d * d;
    const int K = dp << 6;
    const int w = threadIdx.x >> 5, lane = threadIdx.x & 31;
    const int P = (blockIdx.x << 3) + w;
    const int i = P >> 6, o = P & 63;
    __half* tw = sm[w];

    const __half* src = g_psiL + (size_t)(i * 64 + o) * 1792 + off;
    for (int j = lane; j < dd; j += 32) tw[j] = src[j];
    __syncwarp();

    const int hdp = dp >> 1;
    const float invh = c_invhdp[l];
    const int tasks = d * hdp;
    const __half hz = __ushort_as_half((unsigned short)0);
    __half* dstBase = g_psiT + c_PT[l] + (size_t)(o * d) * K + i * dp;
    for (int t = lane; t < tasks; t += 32) {
        int v = (int)((float)t * invh + 0.001f);
        int c = t - v * hdp;
        int u0 = c << 1;
        __half h0 = (u0 < d) ? tw[u0 * d + v] : hz;
        __half h1 = (u0 + 1 < d) ? tw[(u0 + 1) * d + v] : hz;
        *(__half2*)(dstBase + (size_t)v * K + u0) = __halves2half2(h0, h1);
    }
}

// ===========================================================================
// so3 GEMM: per l, C[bm,ov] = sum_k xT[bm,k] * psiT[ov,k], K=64*dp (alpha
// pre-folded into psiT). Epilogue staged via smem, m-contiguous runs.
// ===========================================================================
__global__ __launch_bounds__(256, 1) void so3_g(float* __restrict__ outg) {
    extern __shared__ float dsm[];
    const uint32_t smem = s2u(dsm);
    const int idx = 945 - blockIdx.x;        // big-l tiles first
    int l = 0;
#pragma unroll
    for (int j = 1; j < 11; ++j) l += (idx >= c_tB[j]);
    const int d = 2 * l + 1;
    const int dp = c_dp[l];
    const int K = dp << 6;
    const int t0 = idx - c_tB[l];
    const int tile_n = (int)((float)t0 * c_invd[l] + 0.01f);  // t0 / d
    const int tile_m = t0 - tile_n * d;

    float acc[4][8][4] = {};
    gemm_core(g_xT + c_XT[l] + (size_t)tile_m * 256 * K,
              g_psiT + c_PT[l] + (size_t)tile_n * 128 * K, K, smem, acc);

    // ---- stage C tile to smem (132KB, pipeline stages now dead) ----
    __syncthreads();
    float* smC = dsm;
    const int lane = threadIdx.x & 31, wid = threadIdx.x >> 5;
    const int wm = wid >> 1, wn = wid & 1;
    const int gid = lane >> 2, tig = lane & 3;
#pragma unroll
    for (int mf = 0; mf < 4; ++mf)
#pragma unroll
        for (int nf = 0; nf < 8; ++nf)
#pragma unroll
            for (int e = 0; e < 4; ++e) {
                int bml = wm * 64 + mf * 16 + gid + ((e >> 1) << 3);
                int ovl = wn * 64 + nf * 8 + (tig << 1) + (e & 1);
                smC[bml * 129 + ovl] = acc[mf][nf][e];
            }
    __syncthreads();

    // ---- write out in m-contiguous runs ----
    const float invd = c_invd[l];
    const int off = c_off[l];
    const int nValid = d << 6;
    const int B0 = tile_m << 8;
    const int b_first = B0 / d;
    const int m_first = B0 - b_first * d;
    const int nb = (B0 + 255) / d - b_first + 1;
    const int tasks = nb << 7;
    const int tid = threadIdx.x;

    for (int t = tid; t < tasks; t += 256) {
        int j = t >> 7, ovl = t & 127;
        int ov = (tile_n << 7) + ovl;
        if (ov >= nValid) continue;
        int o = (int)((float)ov * invd + 0.01f);
        int v = ov - o * d;
        int start = j * d - m_first;
        int mlo = (start < 0) ? -start : 0;
        int mhi = d;
        { int lim = 256 - start; if (lim < mhi) mhi = lim; }
        if (mlo >= mhi) continue;
        float* gp = outg + (size_t)(b_first + j) * BSTRIDE + o * IR + off + v * d;
        const int sbase = start * 129 + ovl;
        int m = mlo;
        while (m < mhi && (((uintptr_t)(gp + m)) & 15u)) { gp[m] = smC[sbase + m * 129]; ++m; }
        for (; m + 4 <= mhi; m += 4) {
            float4 f;
            f.x = smC[sbase + m * 129];
            f.y = smC[sbase + (m + 1) * 129];
            f.z = smC[sbase + (m + 2) * 129];
            f.w = smC[sbase + (m + 3) * 129];
            *(float4*)(gp + m) = f;
        }
        for (; m < mhi; ++m) gp[m] = smC[sbase + m * 129];
    }
}

// ---------------------------------------------------------------------------
extern "C" void kernel_launch(void* const* d_in, const int* in_sizes, int n_in,
                              void* d_out, int out_size) {
    const float *x = nullptr, *D = nullptr, *w = nullptr;
    for (int i = 0; i < n_in; ++i) {
        int s = in_sizes[i];
        if (s == 256 * 64 * IR) x = (const float*)d_in[i];
        else if (s == 512 * IR) D = (const float*)d_in[i];
        else if (s == 64 * 64 * 512) w = (const float*)d_in[i];
    }

    cudaFuncSetAttribute(psi_g, cudaFuncAttributeMaxDynamicSharedMemorySize, SMEM_TOTAL);
    cudaFuncSetAttribute(so3_g, cudaFuncAttributeMaxDynamicSharedMemorySize, SMEM_TOTAL);

    wround_g<<<2048, 256>>>(w);
    dt_g<<<dim3(56, 16), 256>>>(D);
    xt_g<<<dim3(2048, 11), 256>>>(x);
    psi_g<<<224, 256, SMEM_TOTAL>>>();
    pT_g<<<dim3(512, 11), 256>>>();
    so3_g<<<946, 256, SMEM_TOTAL>>>((float*)d_out);
}

// round 11
// speedup vs baseline: 1.4789x; 1.0144x over previous
#include <cuda_runtime.h>
#include <cuda_fp16.h>
#include <cstdint>

#define IR 1771
#define BSTRIDE (64 * IR)
#define SCALE_PSI 0.04419417382415922f   // 1/sqrt(512)

// ---------------- device scratch (all zero-initialized .bss) ----------------
__device__ __align__(16) __half g_wT[64 * 64 * 512];   // rn w  [p=4096][k=512]
__device__ __align__(16) __half g_DT[1792 * 512];      // rn D^T [m pad 1792][n=512]
__device__ __align__(16) __half g_psiL[4096 * 1792];   // psi*alpha linear [p][m]
__device__ __align__(16) __half g_psiT[7843840];       // per-l [ov][k=i*dp+u]
__device__ __align__(16) __half g_xT[31002624];        // per-l [bm][k=i*dp+u]

__constant__ int c_off[11] = {0, 1, 10, 35, 84, 165, 286, 455, 680, 969, 1330};
__constant__ int c_dp[11]  = {2, 4, 6, 8, 10, 12, 14, 16, 18, 20, 22};
__constant__ int c_PT[11]  = {0, 8192, 57344, 180224, 409600, 778240, 1318912,
                              2064384, 3047424, 4300800, 5857280};
__constant__ int c_XT[11]  = {0, 32768, 229376, 720896, 1638400, 3112960, 5275648,
                              8257536, 12189696, 17203200, 23429120};
// cumulative d*ceil(d/2) block counts (946 total)
__constant__ int c_tB[12]  = {0, 1, 7, 22, 50, 95, 161, 252, 372, 525, 715, 946};
__constant__ float c_invd[11]   = {1.0f, 1.0f/3.0f, 0.2f, 1.0f/7.0f, 1.0f/9.0f, 1.0f/11.0f,
                                   1.0f/13.0f, 1.0f/15.0f, 1.0f/17.0f, 1.0f/19.0f, 1.0f/21.0f};
__constant__ float c_invhdp[11] = {1.0f, 0.5f, 1.0f/3.0f, 0.25f, 0.2f, 1.0f/6.0f,
                                   1.0f/7.0f, 0.125f, 1.0f/9.0f, 0.1f, 1.0f/11.0f};
__constant__ float c_alpha[11]  = {0.125f, 0.072168784f, 0.055901699f, 0.047245559f,
                                   0.041666667f, 0.037688918f, 0.034668700f, 0.032274861f,
                                   0.030316953f, 0.028676967f, 0.027277236f};

// ---------------------------------------------------------------- helpers
__device__ __forceinline__ uint32_t s2u(const void* p) {
    uint32_t a;
    asm("{ .reg .u64 t; cvta.to.shared.u64 t, %1; cvt.u32.u64 %0, t; }" : "=r"(a) : "l"(p));
    return a;
}
__device__ __forceinline__ void mma16(float* c, const uint32_t* a, const uint32_t* b) {
    asm volatile(
        "mma.sync.aligned.m16n8k16.row.col.f32.f16.f16.f32 "
        "{%0,%1,%2,%3}, {%4,%5,%6,%7}, {%8,%9}, {%0,%1,%2,%3};"
        : "+f"(c[0]), "+f"(c[1]), "+f"(c[2]), "+f"(c[3])
        : "r"(a[0]), "r"(a[1]), "r"(a[2]), "r"(a[3]), "r"(b[0]), "r"(b[1]));
}
__device__ __forceinline__ void ldsm4(uint32_t* r, uint32_t addr) {
    asm volatile("ldmatrix.sync.aligned.m8n8.x4.shared.b16 {%0,%1,%2,%3}, [%4];"
                 : "=r"(r[0]), "=r"(r[1]), "=r"(r[2]), "=r"(r[3]) : "r"(addr));
}
__device__ __forceinline__ void cpa16(uint32_t dst, const void* src) {
    asm volatile("cp.async.cg.shared.global [%0], [%1], 16;" :: "r"(dst), "l"(src));
}
#define CP_COMMIT asm volatile("cp.async.commit_group;" ::: "memory")
#define CP_WAIT0  asm volatile("cp.async.wait_group 0;" ::: "memory")

#define STAGE_B 98304u          // 64KB A (256 rows x 256B) + 32KB B (128 rows)
#define SMEM_TOTAL (2u * STAGE_B)   // 192KB, 2-stage double buffer

// ===========================================================================
// Dense fp16 GEMM core: C[256,128] += A[256,K] * B[128,K]^T (fp32 accum).
// 8 warps (4m x 2n), warp tile 64x64, K-chunk 128, 2-stage cp.async double
// buffer (wait_group 0), single-buffer ldmatrix fragments, swizzled 256B rows.
// ===========================================================================
__device__ __forceinline__ void gemm_core(const __half* __restrict__ A,
                                          const __half* __restrict__ B,
                                          int K, uint32_t smem,
                                          float (&acc)[4][8][4]) {
    const int tid = threadIdx.x;
    const int lane = tid & 31, wid = tid >> 5;
    const int wm = wid >> 1, wn = wid & 1;

    // loader: seg s4 = tid&15 (16B seg of a 256B row), base row rb = tid>>4
    const int s4 = tid & 15, rb = tid >> 4;
    const __half* srcA = A + (size_t)rb * K + (s4 << 3);
    const __half* srcB = B + (size_t)rb * K + (s4 << 3);
    const uint32_t swz = ((uint32_t)(((s4 & 7) ^ (rb & 7)) | (s4 & 8))) << 4;
    const uint32_t dbA = (uint32_t)rb * 256u + swz;            // A rows rb+16q, q 0..15
    const uint32_t dbB = 65536u + (uint32_t)rb * 256u + swz;   // B rows rb+16q, q 0..7

    // ldmatrix lane geometry: lane L supplies row L&7 of matrix L>>3
    const int Lm = lane & 7, Lmat = lane >> 3;
    const uint32_t h = (uint32_t)(Lmat >> 1);
    uint32_t rowA[4], rowB[4];
#pragma unroll
    for (int mf = 0; mf < 4; ++mf)
        rowA[mf] = (uint32_t)(wm * 64 + mf * 16 + ((Lmat & 1) << 3) + Lm);
#pragma unroll
    for (int pr = 0; pr < 4; ++pr)
        rowB[pr] = (uint32_t)(wn * 64 + pr * 16 + ((Lmat & 1) << 3) + Lm);

    const int nCk = K >> 7;

    // prologue: chunk 0 -> stage 0
#pragma unroll
    for (int q = 0; q < 16; ++q) cpa16(smem + dbA + (uint32_t)q * 4096u, srcA + (size_t)(q << 4) * K);
#pragma unroll
    for (int q = 0; q < 8; ++q)  cpa16(smem + dbB + (uint32_t)q * 4096u, srcB + (size_t)(q << 4) * K);
    CP_COMMIT;

    for (int ck = 0; ck < nCk; ++ck) {
        CP_WAIT0;          // chunk ck resident (only outstanding group)
        __syncthreads();   // publish ck to all warps; all done with other stage

        const int nk = ck + 1;
        if (nk < nCk) {
            uint32_t st = smem + (uint32_t)(nk & 1) * STAGE_B;
#pragma unroll
            for (int q = 0; q < 16; ++q)
                cpa16(st + dbA + (uint32_t)q * 4096u, srcA + (size_t)(q << 4) * K + nk * 128);
#pragma unroll
            for (int q = 0; q < 8; ++q)
                cpa16(st + dbB + (uint32_t)q * 4096u, srcB + (size_t)(q << 4) * K + nk * 128);
        }
        CP_COMMIT;

        const uint32_t stA = smem + (uint32_t)(ck & 1) * STAGE_B;
        const uint32_t stB = stA + 65536u;
#pragma unroll
        for (int ks = 0; ks < 8; ++ks) {
            uint32_t af[4][4], bf[4][4];
            const uint32_t sg = (uint32_t)(ks << 1) | h;
            const uint32_t sgl = sg & 7u, sgh = (sg & 8u) << 4;
#pragma unroll
            for (int mf = 0; mf < 4; ++mf)
                ldsm4(af[mf], stA + rowA[mf] * 256u + sgh + (((sgl ^ (rowA[mf] & 7u))) << 4));
#pragma unroll
            for (int pr = 0; pr < 4; ++pr)
                ldsm4(bf[pr], stB + rowB[pr] * 256u + sgh + (((sgl ^ (rowB[pr] & 7u))) << 4));
#pragma unroll
            for (int mf = 0; mf < 4; ++mf)
#pragma unroll
                for (int nf = 0; nf < 8; ++nf) {
                    uint32_t b2[2] = { bf[nf >> 1][nf & 1], bf[nf >> 1][(nf & 1) + 2] };
                    mma16(acc[mf][nf], af[mf], b2);
                }
        }
    }
}

// ===========================================================================
// prep kernels
// ===========================================================================
__global__ __launch_bounds__(256) void wround_g(const float* __restrict__ wg) {
    int j = (blockIdx.x * 256 + threadIdx.x) << 2;
    float4 v = *(const float4*)(wg + j);
    g_wT[j + 0] = __float2half_rn(v.x);
    g_wT[j + 1] = __float2half_rn(v.y);
    g_wT[j + 2] = __float2half_rn(v.z);
    g_wT[j + 3] = __float2half_rn(v.w);
}

__global__ __launch_bounds__(256) void dt_g(const float* __restrict__ Dg) {
    __shared__ float t[32][33];
    const int m0 = blockIdx.x << 5, n0 = blockIdx.y << 5;
    const int tx = threadIdx.x & 31, ty = threadIdx.x >> 5;
#pragma unroll
    for (int r = 0; r < 32; r += 8) {
        int m = m0 + tx, n = n0 + ty + r;
        t[ty + r][tx] = (m < IR) ? Dg[(size_t)n * IR + m] : 0.0f;
    }
    __syncthreads();
#pragma unroll
    for (int r = 0; r < 32; r += 8) {
        int m = m0 + ty + r, n = n0 + tx;
        if (m < IR) g_DT[(size_t)m * 512 + n] = __float2half_rn(t[tx][ty + r]);
    }
}

// fused over l: one warp per (b,i); xT[l][(b*d+m)][i*dp+u] = rn(x[b][i][off+u*d+m])
__global__ __launch_bounds__(256) void xt_g(const float* __restrict__ xg) {
    __shared__ float tile[8][448];
    const int w = threadIdx.x >> 5, lane = threadIdx.x & 31;
    const int P = (blockIdx.x << 3) + w;
    const int b = P >> 6, i = P & 63;
    float* tw = tile[w];
    const float* src = xg + (size_t)b * BSTRIDE + i * IR;

    for (int l = 0; l < 11; ++l) {
        const int d = 2 * l + 1, off = c_off[l], dp = c_dp[l], K = dp << 6, dd = d * d;
        for (int j = lane; j < dd; j += 32) tw[j] = src[off + j];
        __syncwarp();
        const float invd = c_invd[l];
        __half* dst = g_xT + c_XT[l] + (size_t)(b * d) * K + i * dp;
        for (int j = lane; j < dd; j += 32) {
            int m = (int)((float)j * invd + 0.01f);
            int u = j - m * d;
            dst[(size_t)m * K + u] = __float2half_rn(tw[u * d + m]);
        }
        __syncwarp();
    }
}

// ===========================================================================
// psi GEMM: psiL[p,m] = alpha_l(m)/sqrt512 * sum_n wT[p,n] * DT[m,n].
// Grid: 16 tm (p/256) x 14 tn (m/128). Coalesced half2 stores.
// ===========================================================================
__global__ __launch_bounds__(256, 1) void psi_g() {
    extern __shared__ float dsm[];
    const uint32_t smem = s2u(dsm);
    const int tm = blockIdx.x & 15, tn = blockIdx.x >> 4;

    float acc[4][8][4] = {};
    gemm_core(g_wT + (size_t)tm * 256 * 512, g_DT + (size_t)tn * 128 * 512, 512, smem, acc);

    const int lane = threadIdx.x & 31, wid = threadIdx.x >> 5;
    const int wm = wid >> 1, wn = wid & 1;
    const int gid = lane >> 2, tig = lane & 3;
    const int pbase = (tm << 8) + wm * 64 + gid;
    const int mbase = (tn << 7) + wn * 64 + (tig << 1);
#pragma unroll
    for (int nf = 0; nf < 8; ++nf) {
        int m = mbase + nf * 8;
        // per-element alpha (pair may straddle an l boundary)
        float a0 = 0.0f, a1 = 0.0f;
        if (m < IR) {
            int l0 = 0;
#pragma unroll
            for (int j = 1; j < 11; ++j) l0 += (m >= c_off[j]);
            a0 = c_alpha[l0] * SCALE_PSI;
            int l1 = (l0 < 10 && (m + 1) >= c_off[l0 + 1]) ? l0 + 1 : l0;
            a1 = ((m + 1) < IR) ? c_alpha[l1] * SCALE_PSI : 0.0f;
        }
#pragma unroll
        for (int mf = 0; mf < 4; ++mf)
#pragma unroll
            for (int i2 = 0; i2 < 2; ++i2) {
                int p = pbase + mf * 16 + (i2 << 3);
                __half2 v2 = __floats2half2_rn(acc[mf][nf][i2 * 2] * a0,
                                               acc[mf][nf][i2 * 2 + 1] * a1);
                *(__half2*)(g_psiL + (size_t)p * 1792 + m) = v2;
            }
    }
}

// ===========================================================================
// pT_g fused over l: one warp per (i,o);
// psiT[l][(o*d+v)][i*dp+u] = psiL[i*64+o][off + u*d + v]  (pad u=d -> 0)
// ===========================================================================
__global__ __launch_bounds__(256) void pT_g() {
    __shared__ __half sm[8][448];
    const int w = threadIdx.x >> 5, lane = threadIdx.x & 31;
    const int P = (blockIdx.x << 3) + w;
    const int i = P >> 6, o = P & 63;
    __half* tw = sm[w];
    const __half* src = g_psiL + (size_t)(i * 64 + o) * 1792;
    const __half hz = __ushort_as_half((unsigned short)0);

    for (int l = 0; l < 11; ++l) {
        const int d = 2 * l + 1, off = c_off[l], dp = c_dp[l], dd = d * d;
        const int K = dp << 6;
        for (int j = lane; j < dd; j += 32) tw[j] = src[off + j];
        __syncwarp();
        const int hdp = dp >> 1;
        const float invh = c_invhdp[l];
        const int tasks = d * hdp;
        __half* dstBase = g_psiT + c_PT[l] + (size_t)(o * d) * K + i * dp;
        for (int t = lane; t < tasks; t += 32) {
            int v = (int)((float)t * invh + 0.001f);
            int c = t - v * hdp;
            int u0 = c << 1;
            __half h0 = (u0 < d) ? tw[u0 * d + v] : hz;
            __half h1 = (u0 + 1 < d) ? tw[(u0 + 1) * d + v] : hz;
            *(__half2*)(dstBase + (size_t)v * K + u0) = __halves2half2(h0, h1);
        }
        __syncwarp();
    }
}

// ===========================================================================
// so3 GEMM: per l, C[bm,ov] = sum_k xT[bm,k] * psiT[ov,k], K=64*dp (alpha
// pre-folded into psiT). Epilogue staged via smem, m-contiguous runs.
// ===========================================================================
__global__ __launch_bounds__(256, 1) void so3_g(float* __restrict__ outg) {
    extern __shared__ float dsm[];
    const uint32_t smem = s2u(dsm);
    const int idx = 945 - blockIdx.x;        // big-l tiles first
    int l = 0;
#pragma unroll
    for (int j = 1; j < 11; ++j) l += (idx >= c_tB[j]);
    const int d = 2 * l + 1;
    const int dp = c_dp[l];
    const int K = dp << 6;
    const int t0 = idx - c_tB[l];
    const int tile_n = (int)((float)t0 * c_invd[l] + 0.01f);  // t0 / d
    const int tile_m = t0 - tile_n * d;

    float acc[4][8][4] = {};
    gemm_core(g_xT + c_XT[l] + (size_t)tile_m * 256 * K,
              g_psiT + c_PT[l] + (size_t)tile_n * 128 * K, K, smem, acc);

    // ---- stage C tile to smem (132KB, pipeline stages now dead) ----
    __syncthreads();
    float* smC = dsm;
    const int lane = threadIdx.x & 31, wid = threadIdx.x >> 5;
    const int wm = wid >> 1, wn = wid & 1;
    const int gid = lane >> 2, tig = lane & 3;
#pragma unroll
    for (int mf = 0; mf < 4; ++mf)
#pragma unroll
        for (int nf = 0; nf < 8; ++nf)
#pragma unroll
            for (int e = 0; e < 4; ++e) {
                int bml = wm * 64 + mf * 16 + gid + ((e >> 1) << 3);
                int ovl = wn * 64 + nf * 8 + (tig << 1) + (e & 1);
                smC[bml * 129 + ovl] = acc[mf][nf][e];
            }
    __syncthreads();

    // ---- write out in m-contiguous runs ----
    const float invd = c_invd[l];
    const int off = c_off[l];
    const int nValid = d << 6;
    const int B0 = tile_m << 8;
    const int b_first = B0 / d;
    const int m_first = B0 - b_first * d;
    const int nb = (B0 + 255) / d - b_first + 1;
    const int tasks = nb << 7;
    const int tid = threadIdx.x;

    for (int t = tid; t < tasks; t += 256) {
        int j = t >> 7, ovl = t & 127;
        int ov = (tile_n << 7) + ovl;
        if (ov >= nValid) continue;
        int o = (int)((float)ov * invd + 0.01f);
        int v = ov - o * d;
        int start = j * d - m_first;
        int mlo = (start < 0) ? -start : 0;
        int mhi = d;
        { int lim = 256 - start; if (lim < mhi) mhi = lim; }
        if (mlo >= mhi) continue;
        float* gp = outg + (size_t)(b_first + j) * BSTRIDE + o * IR + off + v * d;
        const int sbase = start * 129 + ovl;
        int m = mlo;
        while (m < mhi && (((uintptr_t)(gp + m)) & 15u)) { gp[m] = smC[sbase + m * 129]; ++m; }
        for (; m + 4 <= mhi; m += 4) {
            float4 f;
            f.x = smC[sbase + m * 129];
            f.y = smC[sbase + (m + 1) * 129];
            f.z = smC[sbase + (m + 2) * 129];
            f.w = smC[sbase + (m + 3) * 129];
            *(float4*)(gp + m) = f;
        }
        for (; m < mhi; ++m) gp[m] = smC[sbase + m * 129];
    }
}

// ---------------------------------------------------------------------------
extern "C" void kernel_launch(void* const* d_in, const int* in_sizes, int n_in,
                              void* d_out, int out_size) {
    const float *x = nullptr, *D = nullptr, *w = nullptr;
    for (int i = 0; i < n_in; ++i) {
        int s = in_sizes[i];
        if (s == 256 * 64 * IR) x = (const float*)d_in[i];
        else if (s == 512 * IR) D = (const float*)d_in[i];
        else if (s == 64 * 64 * 512) w = (const float*)d_in[i];
    }

    cudaFuncSetAttribute(psi_g, cudaFuncAttributeMaxDynamicSharedMemorySize, SMEM_TOTAL);
    cudaFuncSetAttribute(so3_g, cudaFuncAttributeMaxDynamicSharedMemorySize, SMEM_TOTAL);

    wround_g<<<2048, 256>>>(w);
    dt_g<<<dim3(56, 16), 256>>>(D);
    xt_g<<<2048, 256>>>(x);
    psi_g<<<224, 256, SMEM_TOTAL>>>();
    pT_g<<<512, 256>>>();
    so3_g<<<946, 256, SMEM_TOTAL>>>((float*)d_out);
}

// round 12
// speedup vs baseline: 1.4798x; 1.0006x over previous
#include <cuda_runtime.h>
#include <cuda_fp16.h>
#include <cstdint>

#define IR 1771
#define BSTRIDE (64 * IR)
#define SCALE_PSI 0.04419417382415922f   // 1/sqrt(512)

// ---------------- device scratch (all zero-initialized .bss) ----------------
__device__ __align__(16) __half g_wT[64 * 64 * 512];   // rn w  [p=4096][k=512]
__device__ __align__(16) __half g_DT[1792 * 512];      // rn D^T [m pad 1792][n=512]
__device__ __align__(16) __half g_psiL[4096 * 1792];   // psi*alpha linear [p][m]
__device__ __align__(16) __half g_psiT[7843840];       // per-l [ov][k=i*dp+u]
__device__ __align__(16) __half g_xT[31002624];        // per-l [bm][k=i*dp+u]

__constant__ int c_off[11] = {0, 1, 10, 35, 84, 165, 286, 455, 680, 969, 1330};
__constant__ int c_dp[11]  = {2, 4, 6, 8, 10, 12, 14, 16, 18, 20, 22};
__constant__ int c_PT[11]  = {0, 8192, 57344, 180224, 409600, 778240, 1318912,
                              2064384, 3047424, 4300800, 5857280};
__constant__ int c_XT[11]  = {0, 32768, 229376, 720896, 1638400, 3112960, 5275648,
                              8257536, 12189696, 17203200, 23429120};
// cumulative d*ceil(d/2) block counts (946 total)
__constant__ int c_tB[12]  = {0, 1, 7, 22, 50, 95, 161, 252, 372, 525, 715, 946};
__constant__ float c_invd[11]   = {1.0f, 1.0f/3.0f, 0.2f, 1.0f/7.0f, 1.0f/9.0f, 1.0f/11.0f,
                                   1.0f/13.0f, 1.0f/15.0f, 1.0f/17.0f, 1.0f/19.0f, 1.0f/21.0f};
__constant__ float c_invhdp[11] = {1.0f, 0.5f, 1.0f/3.0f, 0.25f, 0.2f, 1.0f/6.0f,
                                   1.0f/7.0f, 0.125f, 1.0f/9.0f, 0.1f, 1.0f/11.0f};
__constant__ float c_alpha[11]  = {0.125f, 0.072168784f, 0.055901699f, 0.047245559f,
                                   0.041666667f, 0.037688918f, 0.034668700f, 0.032274861f,
                                   0.030316953f, 0.028676967f, 0.027277236f};

// ---------------------------------------------------------------- helpers
__device__ __forceinline__ uint32_t s2u(const void* p) {
    uint32_t a;
    asm("{ .reg .u64 t; cvta.to.shared.u64 t, %1; cvt.u32.u64 %0, t; }" : "=r"(a) : "l"(p));
    return a;
}
__device__ __forceinline__ void mma16(float* c, const uint32_t* a, const uint32_t* b) {
    asm volatile(
        "mma.sync.aligned.m16n8k16.row.col.f32.f16.f16.f32 "
        "{%0,%1,%2,%3}, {%4,%5,%6,%7}, {%8,%9}, {%0,%1,%2,%3};"
        : "+f"(c[0]), "+f"(c[1]), "+f"(c[2]), "+f"(c[3])
        : "r"(a[0]), "r"(a[1]), "r"(a[2]), "r"(a[3]), "r"(b[0]), "r"(b[1]));
}
__device__ __forceinline__ void ldsm4(uint32_t* r, uint32_t addr) {
    asm volatile("ldmatrix.sync.aligned.m8n8.x4.shared.b16 {%0,%1,%2,%3}, [%4];"
                 : "=r"(r[0]), "=r"(r[1]), "=r"(r[2]), "=r"(r[3]) : "r"(addr));
}
__device__ __forceinline__ void cpa16(uint32_t dst, const void* src) {
    asm volatile("cp.async.cg.shared.global [%0], [%1], 16;" :: "r"(dst), "l"(src));
}
#define CP_COMMIT asm volatile("cp.async.commit_group;" ::: "memory")
#define CP_WAIT0  asm volatile("cp.async.wait_group 0;" ::: "memory")

#define STAGE_B 98304u          // 64KB A (256 rows x 256B) + 32KB B (128 rows)
#define SMEM_TOTAL (2u * STAGE_B)   // 192KB, 2-stage double buffer

// ===========================================================================
// Dense fp16 GEMM core: C[256,128] += A[256,K] * B[128,K]^T (fp32 accum).
// 16 warps (4m x 4n), warp tile 64x32, K-chunk 128, 2-stage cp.async double
// buffer (wait_group 0), single-buffer ldmatrix fragments, swizzled 256B rows.
// ===========================================================================
__device__ __forceinline__ void gemm_core(const __half* __restrict__ A,
                                          const __half* __restrict__ B,
                                          int K, uint32_t smem,
                                          float (&acc)[4][4][4]) {
    const int tid = threadIdx.x;
    const int lane = tid & 31, wid = tid >> 5;
    const int wm = wid >> 2, wn = wid & 3;

    // loader: seg s4 = tid&15 (16B seg of a 256B row), base row rb = tid>>4 (0..31)
    const int s4 = tid & 15, rb = tid >> 4;
    const __half* srcA = A + (size_t)rb * K + (s4 << 3);
    const __half* srcB = B + (size_t)rb * K + (s4 << 3);
    const uint32_t swz = ((uint32_t)(((s4 & 7) ^ (rb & 7)) | (s4 & 8))) << 4;
    const uint32_t dbA = (uint32_t)rb * 256u + swz;            // A rows rb+32q, q 0..7
    const uint32_t dbB = 65536u + (uint32_t)rb * 256u + swz;   // B rows rb+32q, q 0..3

    // ldmatrix lane geometry: lane L supplies row L&7 of matrix L>>3
    const int Lm = lane & 7, Lmat = lane >> 3;
    const uint32_t h = (uint32_t)(Lmat >> 1);
    uint32_t rowA[4], rowB[2];
#pragma unroll
    for (int mf = 0; mf < 4; ++mf)
        rowA[mf] = (uint32_t)(wm * 64 + mf * 16 + ((Lmat & 1) << 3) + Lm);
#pragma unroll
    for (int pr = 0; pr < 2; ++pr)
        rowB[pr] = (uint32_t)(wn * 32 + pr * 16 + ((Lmat & 1) << 3) + Lm);

    const int nCk = K >> 7;

    // prologue: chunk 0 -> stage 0
#pragma unroll
    for (int q = 0; q < 8; ++q) cpa16(smem + dbA + (uint32_t)q * 8192u, srcA + (size_t)(q << 5) * K);
#pragma unroll
    for (int q = 0; q < 4; ++q) cpa16(smem + dbB + (uint32_t)q * 8192u, srcB + (size_t)(q << 5) * K);
    CP_COMMIT;

    for (int ck = 0; ck < nCk; ++ck) {
        CP_WAIT0;          // chunk ck resident (only outstanding group)
        __syncthreads();   // publish ck to all warps; all done with other stage

        const int nk = ck + 1;
        if (nk < nCk) {
            uint32_t st = smem + (uint32_t)(nk & 1) * STAGE_B;
#pragma unroll
            for (int q = 0; q < 8; ++q)
                cpa16(st + dbA + (uint32_t)q * 8192u, srcA + (size_t)(q << 5) * K + nk * 128);
#pragma unroll
            for (int q = 0; q < 4; ++q)
                cpa16(st + dbB + (uint32_t)q * 8192u, srcB + (size_t)(q << 5) * K + nk * 128);
        }
        CP_COMMIT;

        const uint32_t stA = smem + (uint32_t)(ck & 1) * STAGE_B;
        const uint32_t stB = stA + 65536u;
#pragma unroll
        for (int ks = 0; ks < 8; ++ks) {
            uint32_t af[4][4], bf[2][4];
            const uint32_t sg = (uint32_t)(ks << 1) | h;
            const uint32_t sgl = sg & 7u, sgh = (sg & 8u) << 4;
#pragma unroll
            for (int mf = 0; mf < 4; ++mf)
                ldsm4(af[mf], stA + rowA[mf] * 256u + sgh + (((sgl ^ (rowA[mf] & 7u))) << 4));
#pragma unroll
            for (int pr = 0; pr < 2; ++pr)
                ldsm4(bf[pr], stB + rowB[pr] * 256u + sgh + (((sgl ^ (rowB[pr] & 7u))) << 4));
#pragma unroll
            for (int mf = 0; mf < 4; ++mf)
#pragma unroll
                for (int nf = 0; nf < 4; ++nf) {
                    uint32_t b2[2] = { bf[nf >> 1][nf & 1], bf[nf >> 1][(nf & 1) + 2] };
                    mma16(acc[mf][nf], af[mf], b2);
                }
        }
    }
}

// ===========================================================================
// prep kernels
// ===========================================================================
__global__ __launch_bounds__(256) void wround_g(const float* __restrict__ wg) {
    int j = (blockIdx.x * 256 + threadIdx.x) << 2;
    float4 v = *(const float4*)(wg + j);
    g_wT[j + 0] = __float2half_rn(v.x);
    g_wT[j + 1] = __float2half_rn(v.y);
    g_wT[j + 2] = __float2half_rn(v.z);
    g_wT[j + 3] = __float2half_rn(v.w);
}

__global__ __launch_bounds__(256) void dt_g(const float* __restrict__ Dg) {
    __shared__ float t[32][33];
    const int m0 = blockIdx.x << 5, n0 = blockIdx.y << 5;
    const int tx = threadIdx.x & 31, ty = threadIdx.x >> 5;
#pragma unroll
    for (int r = 0; r < 32; r += 8) {
        int m = m0 + tx, n = n0 + ty + r;
        t[ty + r][tx] = (m < IR) ? Dg[(size_t)n * IR + m] : 0.0f;
    }
    __syncthreads();
#pragma unroll
    for (int r = 0; r < 32; r += 8) {
        int m = m0 + ty + r, n = n0 + tx;
        if (m < IR) g_DT[(size_t)m * 512 + n] = __float2half_rn(t[tx][ty + r]);
    }
}

// fused over l: one warp per (b,i); xT[l][(b*d+m)][i*dp+u] = rn(x[b][i][off+u*d+m])
__global__ __launch_bounds__(256) void xt_g(const float* __restrict__ xg) {
    __shared__ float tile[8][448];
    const int w = threadIdx.x >> 5, lane = threadIdx.x & 31;
    const int P = (blockIdx.x << 3) + w;
    const int b = P >> 6, i = P & 63;
    float* tw = tile[w];
    const float* src = xg + (size_t)b * BSTRIDE + i * IR;

    for (int l = 0; l < 11; ++l) {
        const int d = 2 * l + 1, off = c_off[l], dp = c_dp[l], K = dp << 6, dd = d * d;
        for (int j = lane; j < dd; j += 32) tw[j] = src[off + j];
        __syncwarp();
        const float invd = c_invd[l];
        __half* dst = g_xT + c_XT[l] + (size_t)(b * d) * K + i * dp;
        for (int j = lane; j < dd; j += 32) {
            int m = (int)((float)j * invd + 0.01f);
            int u = j - m * d;
            dst[(size_t)m * K + u] = __float2half_rn(tw[u * d + m]);
        }
        __syncwarp();
    }
}

// ===========================================================================
// psi GEMM: psiL[p,m] = alpha_l(m)/sqrt512 * sum_n wT[p,n] * DT[m,n].
// Grid: 16 tm (p/256) x 14 tn (m/128). Coalesced half2 stores.
// ===========================================================================
__global__ __launch_bounds__(512, 1) void psi_g() {
    extern __shared__ float dsm[];
    const uint32_t smem = s2u(dsm);
    const int tm = blockIdx.x & 15, tn = blockIdx.x >> 4;

    float acc[4][4][4] = {};
    gemm_core(g_wT + (size_t)tm * 256 * 512, g_DT + (size_t)tn * 128 * 512, 512, smem, acc);

    const int lane = threadIdx.x & 31, wid = threadIdx.x >> 5;
    const int wm = wid >> 2, wn = wid & 3;
    const int gid = lane >> 2, tig = lane & 3;
    const int pbase = (tm << 8) + wm * 64 + gid;
    const int mbase = (tn << 7) + wn * 32 + (tig << 1);
#pragma unroll
    for (int nf = 0; nf < 4; ++nf) {
        int m = mbase + nf * 8;
        // per-element alpha (pair may straddle an l boundary)
        float a0 = 0.0f, a1 = 0.0f;
        if (m < IR) {
            int l0 = 0;
#pragma unroll
            for (int j = 1; j < 11; ++j) l0 += (m >= c_off[j]);
            a0 = c_alpha[l0] * SCALE_PSI;
            int l1 = (l0 < 10 && (m + 1) >= c_off[l0 + 1]) ? l0 + 1 : l0;
            a1 = ((m + 1) < IR) ? c_alpha[l1] * SCALE_PSI : 0.0f;
        }
#pragma unroll
        for (int mf = 0; mf < 4; ++mf)
#pragma unroll
            for (int i2 = 0; i2 < 2; ++i2) {
                int p = pbase + mf * 16 + (i2 << 3);
                __half2 v2 = __floats2half2_rn(acc[mf][nf][i2 * 2] * a0,
                                               acc[mf][nf][i2 * 2 + 1] * a1);
                *(__half2*)(g_psiL + (size_t)p * 1792 + m) = v2;
            }
    }
}

// ===========================================================================
// pT_g fused over l: one warp per (i,o);
// psiT[l][(o*d+v)][i*dp+u] = psiL[i*64+o][off + u*d + v]  (pad u=d -> 0)
// ===========================================================================
__global__ __launch_bounds__(256) void pT_g() {
    __shared__ __half sm[8][448];
    const int w = threadIdx.x >> 5, lane = threadIdx.x & 31;
    const int P = (blockIdx.x << 3) + w;
    const int i = P >> 6, o = P & 63;
    __half* tw = sm[w];
    const __half* src = g_psiL + (size_t)(i * 64 + o) * 1792;
    const __half hz = __ushort_as_half((unsigned short)0);

    for (int l = 0; l < 11; ++l) {
        const int d = 2 * l + 1, off = c_off[l], dp = c_dp[l], dd = d * d;
        const int K = dp << 6;
        for (int j = lane; j < dd; j += 32) tw[j] = src[off + j];
        __syncwarp();
        const int hdp = dp >> 1;
        const float invh = c_invhdp[l];
        const int tasks = d * hdp;
        __half* dstBase = g_psiT + c_PT[l] + (size_t)(o * d) * K + i * dp;
        for (int t = lane; t < tasks; t += 32) {
            int v = (int)((float)t * invh + 0.001f);
            int c = t - v * hdp;
            int u0 = c << 1;
            __half h0 = (u0 < d) ? tw[u0 * d + v] : hz;
            __half h1 = (u0 + 1 < d) ? tw[(u0 + 1) * d + v] : hz;
            *(__half2*)(dstBase + (size_t)v * K + u0) = __halves2half2(h0, h1);
        }
        __syncwarp();
    }
}

// ===========================================================================
// so3 GEMM: per l, C[bm,ov] = sum_k xT[bm,k] * psiT[ov,k], K=64*dp (alpha
// pre-folded into psiT). Epilogue staged via smem, m-contiguous runs.
// ===========================================================================
__global__ __launch_bounds__(512, 1) void so3_g(float* __restrict__ outg) {
    extern __shared__ float dsm[];
    const uint32_t smem = s2u(dsm);
    const int idx = 945 - blockIdx.x;        // big-l tiles first
    int l = 0;
#pragma unroll
    for (int j = 1; j < 11; ++j) l += (idx >= c_tB[j]);
    const int d = 2 * l + 1;
    const int dp = c_dp[l];
    const int K = dp << 6;
    const int t0 = idx - c_tB[l];
    const int tile_n = (int)((float)t0 * c_invd[l] + 0.01f);  // t0 / d
    const int tile_m = t0 - tile_n * d;

    float acc[4][4][4] = {};
    gemm_core(g_xT + c_XT[l] + (size_t)tile_m * 256 * K,
              g_psiT + c_PT[l] + (size_t)tile_n * 128 * K, K, smem, acc);

    // ---- stage C tile to smem (132KB, pipeline stages now dead) ----
    __syncthreads();
    float* smC = dsm;
    const int lane = threadIdx.x & 31, wid = threadIdx.x >> 5;
    const int wm = wid >> 2, wn = wid & 3;
    const int gid = lane >> 2, tig = lane & 3;
#pragma unroll
    for (int mf = 0; mf < 4; ++mf)
#pragma unroll
        for (int nf = 0; nf < 4; ++nf)
#pragma unroll
            for (int e = 0; e < 4; ++e) {
                int bml = wm * 64 + mf * 16 + gid + ((e >> 1) << 3);
                int ovl = wn * 32 + nf * 8 + (tig << 1) + (e & 1);
                smC[bml * 129 + ovl] = acc[mf][nf][e];
            }
    __syncthreads();

    // ---- write out in m-contiguous runs ----
    const float invd = c_invd[l];
    const int off = c_off[l];
    const int nValid = d << 6;
    const int B0 = tile_m << 8;
    const int b_first = B0 / d;
    const int m_first = B0 - b_first * d;
    const int nb = (B0 + 255) / d - b_first + 1;
    const int tasks = nb << 7;
    const int tid = threadIdx.x;

    for (int t = tid; t < tasks; t += 512) {
        int j = t >> 7, ovl = t & 127;
        int ov = (tile_n << 7) + ovl;
        if (ov >= nValid) continue;
        int o = (int)((float)ov * invd + 0.01f);
        int v = ov - o * d;
        int start = j * d - m_first;
        int mlo = (start < 0) ? -start : 0;
        int mhi = d;
        { int lim = 256 - start; if (lim < mhi) mhi = lim; }
        if (mlo >= mhi) continue;
        float* gp = outg + (size_t)(b_first + j) * BSTRIDE + o * IR + off + v * d;
        const int sbase = start * 129 + ovl;
        int m = mlo;
        while (m < mhi && (((uintptr_t)(gp + m)) & 15u)) { gp[m] = smC[sbase + m * 129]; ++m; }
        for (; m + 4 <= mhi; m += 4) {
            float4 f;
            f.x = smC[sbase + m * 129];
            f.y = smC[sbase + (m + 1) * 129];
            f.z = smC[sbase + (m + 2) * 129];
            f.w = smC[sbase + (m + 3) * 129];
            *(float4*)(gp + m) = f;
        }
        for (; m < mhi; ++m) gp[m] = smC[sbase + m * 129];
    }
}

// ---------------------------------------------------------------------------
extern "C" void kernel_launch(void* const* d_in, const int* in_sizes, int n_in,
                              void* d_out, int out_size) {
    const float *x = nullptr, *D = nullptr, *w = nullptr;
    for (int i = 0; i < n_in; ++i) {
        int s = in_sizes[i];
        if (s == 256 * 64 * IR) x = (const float*)d_in[i];
        else if (s == 512 * IR) D = (const float*)d_in[i];
        else if (s == 64 * 64 * 512) w = (const float*)d_in[i];
    }

    cudaFuncSetAttribute(psi_g, cudaFuncAttributeMaxDynamicSharedMemorySize, SMEM_TOTAL);
    cudaFuncSetAttribute(so3_g, cudaFuncAttributeMaxDynamicSharedMemorySize, SMEM_TOTAL);

    wround_g<<<2048, 256>>>(w);
    dt_g<<<dim3(56, 16), 256>>>(D);
    xt_g<<<2048, 256>>>(x);
    psi_g<<<224, 512, SMEM_TOTAL>>>();
    pT_g<<<512, 256>>>();
    so3_g<<<946, 512, SMEM_TOTAL>>>((float*)d_out);
}